// round 9
// baseline (speedup 1.0000x reference)
#include <cuda_runtime.h>
#include <cuda_bf16.h>
#include <cuda_fp16.h>
#include <cstdint>

#define NN    8192
#define CC    128
#define KNBR  7
#define HALFN 4096
#define NCAND 16
#define NT    (HALFN / 128)

typedef unsigned long long ull;

// ---------------- device scratch ----------------
__device__ float g_skip[NN * CC];
__device__ float g_h[NN * CC];
__device__ float g_acc[2 * NN * CC];
__device__ float g_l[2 * NN];
__device__ float g_norm[NN];
__device__ float g_cv16[2 * NN * NCAND];
__device__ int   g_ci16[2 * NN * NCAND];
__device__ int   g_idx[NN * KNBR];
__device__ float g_m1[NN * CC];
__device__ float g_h1[NN * CC];
__device__ float g_m2[NN];
__device__ __nv_bfloat16 g_qb0[NN * CC], g_qb1[NN * CC];
__device__ __nv_bfloat16 g_kb0[NN * CC], g_kb1[NN * CC];
__device__ __half        g_vh[NN * CC];
__device__ __nv_bfloat16 g_hb0[NN * CC];

// ---------------- packed fp32x2 (SIMT GEMMs) ----------------
__device__ __forceinline__ ull ffma2(ull a, ull b, ull c) {
    ull d;
    asm("fma.rn.f32x2 %0, %1, %2, %3;" : "=l"(d) : "l"(a), "l"(b), "l"(c));
    return d;
}
__device__ __forceinline__ ull dup2(float x) {
    ull d;
    asm("mov.b64 %0, {%1, %1};" : "=l"(d) : "f"(x));
    return d;
}
__device__ __forceinline__ float2 upk(ull v) {
    float2 r;
    asm("mov.b64 {%0, %1}, %2;" : "=f"(r.x), "=f"(r.y) : "l"(v));
    return r;
}

// ---------------- mma / ldmatrix / cp.async helpers ----------------
__device__ __forceinline__ uint32_t smem_u32(const void* p) {
    uint32_t a;
    asm("{ .reg .u64 t; cvta.to.shared.u64 t, %1; cvt.u32.u64 %0, t; }" : "=r"(a) : "l"(p));
    return a;
}
__device__ __forceinline__ void ldsm4(uint32_t* r, uint32_t a) {
    asm volatile("ldmatrix.sync.aligned.m8n8.x4.shared.b16 {%0,%1,%2,%3}, [%4];"
                 : "=r"(r[0]), "=r"(r[1]), "=r"(r[2]), "=r"(r[3]) : "r"(a));
}
__device__ __forceinline__ void ldsm4t(uint32_t* r, uint32_t a) {
    asm volatile("ldmatrix.sync.aligned.m8n8.x4.trans.shared.b16 {%0,%1,%2,%3}, [%4];"
                 : "=r"(r[0]), "=r"(r[1]), "=r"(r[2]), "=r"(r[3]) : "r"(a));
}
__device__ __forceinline__ void mma16816(float* c, const uint32_t* a, uint32_t b0, uint32_t b1) {
    asm volatile(
        "mma.sync.aligned.m16n8k16.row.col.f32.bf16.bf16.f32 "
        "{%0,%1,%2,%3}, {%4,%5,%6,%7}, {%8,%9}, {%0,%1,%2,%3};"
        : "+f"(c[0]), "+f"(c[1]), "+f"(c[2]), "+f"(c[3])
        : "r"(a[0]), "r"(a[1]), "r"(a[2]), "r"(a[3]), "r"(b0), "r"(b1));
}
// first-touch variant: d = a*b + 0 (no accumulator zeroing needed)
__device__ __forceinline__ void mma16816z(float* d, const uint32_t* a, uint32_t b0, uint32_t b1) {
    asm volatile(
        "mma.sync.aligned.m16n8k16.row.col.f32.bf16.bf16.f32 "
        "{%0,%1,%2,%3}, {%4,%5,%6,%7}, {%8,%9}, {%10,%10,%10,%10};"
        : "=f"(d[0]), "=f"(d[1]), "=f"(d[2]), "=f"(d[3])
        : "r"(a[0]), "r"(a[1]), "r"(a[2]), "r"(a[3]), "r"(b0), "r"(b1), "f"(0.f));
}
__device__ __forceinline__ void mma16816h(float* c, const uint32_t* a, uint32_t b0, uint32_t b1) {
    asm volatile(
        "mma.sync.aligned.m16n8k16.row.col.f32.f16.f16.f32 "
        "{%0,%1,%2,%3}, {%4,%5,%6,%7}, {%8,%9}, {%0,%1,%2,%3};"
        : "+f"(c[0]), "+f"(c[1]), "+f"(c[2]), "+f"(c[3])
        : "r"(a[0]), "r"(a[1]), "r"(a[2]), "r"(a[3]), "r"(b0), "r"(b1));
}
#define CP_COMMIT() asm volatile("cp.async.commit_group;" ::: "memory")
#define CP_WAIT(n)  asm volatile("cp.async.wait_group %0;" :: "n"(n) : "memory")

__device__ __forceinline__ uint32_t pack_bf(float x, float y) {
    __nv_bfloat162 t = __floats2bfloat162_rn(x, y);
    return *reinterpret_cast<uint32_t*>(&t);
}
__device__ __forceinline__ uint32_t pack_h(float x, float y) {
    __half2 t = __floats2half2_rn(x, y);
    return *reinterpret_cast<uint32_t*>(&t);
}
__device__ __forceinline__ void split_pair(float x, float y, uint32_t& p0, uint32_t& p1) {
    __nv_bfloat16 bx = __float2bfloat16_rn(x), by = __float2bfloat16_rn(y);
    __nv_bfloat162 t; t.x = bx; t.y = by;
    p0 = *reinterpret_cast<uint32_t*>(&t);
    p1 = pack_bf(x - __bfloat162float(bx), y - __bfloat162float(by));
}
__device__ __forceinline__ void split_pair_h(float x, float y, uint32_t& p0, uint32_t& p1) {
    __half hx = __float2half_rn(x), hy = __float2half_rn(y);
    __half2 t; t.x = hx; t.y = hy;
    p0 = *reinterpret_cast<uint32_t*>(&t);
    p1 = pack_h(x - __half2float(hx), y - __half2float(hy));
}
// async 128x128 16-bit tile -> smem rows of 272B
__device__ __forceinline__ void ld_tile_async(uint32_t dst, const void* __restrict__ srcv, int tid) {
    const char* src = reinterpret_cast<const char*>(srcv);
    #pragma unroll
    for (int i = 0; i < 8; i++) {
        int idx = tid + i * 256;
        int row = idx >> 4, ch = idx & 15;
        asm volatile("cp.async.cg.shared.global [%0], [%1], 16;" ::
            "r"(dst + (uint32_t)(row * 272 + ch * 16)), "l"(src + (size_t)row * CC * 2 + ch * 16) : "memory");
    }
}
// register top-8 insert
__device__ __forceinline__ void ins8(float* tv, int* ti, float v, int idx) {
    #pragma unroll
    for (int t = 0; t < 8; t++) {
        if (v > tv[t]) {
            float a = tv[t]; tv[t] = v; v = a;
            int   b = ti[t]; ti[t] = idx; idx = b;
        }
    }
}

// ---------------- K1: fused projections -> bf16 splits (q,k), fp16 (v), skip ----------------
__global__ __launch_bounds__(256) void proj_kernel(
    const float* __restrict__ x,
    const float* __restrict__ Wq, const float* __restrict__ bq,
    const float* __restrict__ Wk, const float* __restrict__ bk,
    const float* __restrict__ Wv, const float* __restrict__ bv,
    const float* __restrict__ Ws, const float* __restrict__ bs)
{
    __shared__ float xs[32 * 129];
    const int tid = threadIdx.x;
    const int r0  = blockIdx.x * 32;
    const float SCALE = 0.08838834764831843f;

    for (int i = tid; i < 32 * CC; i += 256) {
        int r = i >> 7, c = i & 127;
        xs[r * 129 + c] = x[(r0 + r) * CC + c];
    }
    __syncthreads();

    const int ri = (tid >> 5) * 4;
    const int c0 = (tid & 31) * 4;

    const float* Wt[4] = {Wq, Wk, Wv, Ws};
    const float* bt[4] = {bq, bk, bv, bs};

    #pragma unroll
    for (int w = 0; w < 4; w++) {
        const float* W = Wt[w];
        ull acc[4][2];
        #pragma unroll
        for (int i = 0; i < 4; i++) { acc[i][0] = 0ULL; acc[i][1] = 0ULL; }

        #pragma unroll 4
        for (int k2 = 0; k2 < CC; k2++) {
            ulonglong2 wp = *reinterpret_cast<const ulonglong2*>(W + k2 * CC + c0);
            #pragma unroll
            for (int dr = 0; dr < 4; dr++) {
                ull x2 = dup2(xs[(ri + dr) * 129 + k2]);
                acc[dr][0] = ffma2(x2, wp.x, acc[dr][0]);
                acc[dr][1] = ffma2(x2, wp.y, acc[dr][1]);
            }
        }
        float4 bb = *reinterpret_cast<const float4*>(bt[w] + c0);
        #pragma unroll
        for (int dr = 0; dr < 4; dr++) {
            float2 a0 = upk(acc[dr][0]), a1 = upk(acc[dr][1]);
            int row = r0 + ri + dr;
            float ox = a0.x + bb.x, oy = a0.y + bb.y;
            float oz = a1.x + bb.z, ow = a1.y + bb.w;
            if (w == 3) {
                float4 o = {ox, oy, oz, ow};
                *reinterpret_cast<float4*>(g_skip + row * CC + c0) = o;
            } else if (w == 2) {
                uint2 u = {pack_h(ox, oy), pack_h(oz, ow)};
                *reinterpret_cast<uint2*>(g_vh + row * CC + c0) = u;
            } else {
                float s = (w == 0) ? SCALE : 1.f;
                ox *= s; oy *= s; oz *= s; ow *= s;
                uint32_t lo0, hi0, lo1, hi1;
                split_pair(ox, oy, lo0, hi0);
                split_pair(oz, ow, lo1, hi1);
                __nv_bfloat16* d0 = (w == 0) ? g_qb0 : g_kb0;
                __nv_bfloat16* d1 = (w == 0) ? g_qb1 : g_kb1;
                uint2 u0 = {lo0, lo1};
                uint2 u1 = {hi0, hi1};
                *reinterpret_cast<uint2*>(d0 + row * CC + c0) = u0;
                *reinterpret_cast<uint2*>(d1 + row * CC + c0) = u1;
            }
        }
    }
}

// ---------------- K2: flash attention, pipelined ----------------
#define AQ0 0
#define AQ1 34816
#define AK0 69632
#define AK1 104448
#define AV0 139264
#define ATTN_SMEM 174080

__global__ __launch_bounds__(256, 1) void attn_mma_kernel()
{
    extern __shared__ __align__(16) char smc[];
    const uint32_t sb = smem_u32(smc);
    const int tid  = threadIdx.x, wid = tid >> 5, lane = tid & 31;
    const int qbase = blockIdx.x * 128;
    const int kofs  = blockIdx.y * HALFN;

    ld_tile_async(sb + AQ0, g_qb0 + (size_t)qbase * CC, tid);
    ld_tile_async(sb + AQ1, g_qb1 + (size_t)qbase * CC, tid);
    CP_COMMIT();
    ld_tile_async(sb + AK0, g_kb0 + (size_t)kofs * CC, tid);
    ld_tile_async(sb + AK1, g_kb1 + (size_t)kofs * CC, tid);
    CP_COMMIT();
    ld_tile_async(sb + AV0, g_vh + (size_t)kofs * CC, tid);
    CP_COMMIT();

    const int r0   = wid * 16;
    const int qrow = lane >> 2, qc = (lane & 3) * 2;
    const int gr0  = qbase + r0 + qrow, gr1 = gr0 + 8;

    const uint32_t aoff = (uint32_t)((r0 + (lane & 15)) * 272 + ((lane >> 4) & 1) * 16);
    const uint32_t boff = (uint32_t)(((lane & 7) + ((lane >> 4) & 1) * 8) * 272 + ((lane >> 3) & 1) * 16);
    const uint32_t voff = (uint32_t)(((lane & 7) + ((lane >> 3) & 1) * 8) * 272 + ((lane >> 4) & 1) * 16);

    float pv[16][4];
    #pragma unroll
    for (int i = 0; i < 16; i++)
        #pragma unroll
        for (int j = 0; j < 4; j++) pv[i][j] = 0.f;
    float l0 = 0.f, l1 = 0.f;

    CP_WAIT(1);
    __syncthreads();

    for (int t = 0; t < NT; t++) {
        const int kb = t * 128;
        const bool more = (t + 1 < NT);

        float sc[16][4];

        // scores: kc=0 writes (zero-C mma), then accumulate
        #pragma unroll
        for (int kc = 0; kc < 8; kc++) {
            uint32_t a0[4], a1[4];
            ldsm4(a0, sb + AQ0 + aoff + kc * 32);
            ldsm4(a1, sb + AQ1 + aoff + kc * 32);
            if (kc == 0) {
                #pragma unroll
                for (int nt2 = 0; nt2 < 8; nt2++) {
                    uint32_t b[4];
                    ldsm4(b, sb + AK0 + (uint32_t)(nt2 * 16 * 272) + boff);
                    mma16816z(sc[2 * nt2],     a0, b[0], b[1]);
                    mma16816z(sc[2 * nt2 + 1], a0, b[2], b[3]);
                    mma16816(sc[2 * nt2],     a1, b[0], b[1]);
                    mma16816(sc[2 * nt2 + 1], a1, b[2], b[3]);
                }
            } else {
                #pragma unroll
                for (int nt2 = 0; nt2 < 8; nt2++) {
                    uint32_t b[4];
                    ldsm4(b, sb + AK0 + (uint32_t)(nt2 * 16 * 272) + boff + kc * 32);
                    mma16816(sc[2 * nt2],     a0, b[0], b[1]);
                    mma16816(sc[2 * nt2 + 1], a0, b[2], b[3]);
                    mma16816(sc[2 * nt2],     a1, b[0], b[1]);
                    mma16816(sc[2 * nt2 + 1], a1, b[2], b[3]);
                }
            }
            #pragma unroll
            for (int nt2 = 0; nt2 < 8; nt2++) {
                uint32_t b[4];
                ldsm4(b, sb + AK1 + (uint32_t)(nt2 * 16 * 272) + boff + kc * 32);
                mma16816(sc[2 * nt2],     a0, b[0], b[1]);
                mma16816(sc[2 * nt2 + 1], a0, b[2], b[3]);
            }
        }

        // exp; diag mask only in the tile containing the diagonal
        float rs0 = 0.f, rs1 = 0.f;
        if (kofs + kb == qbase) {
            #pragma unroll
            for (int nt = 0; nt < 16; nt++) {
                int gc = kofs + kb + nt * 8 + qc;
                float e0 = (gr0 == gc)     ? 0.f : __expf(sc[nt][0]);
                float e1 = (gr0 == gc + 1) ? 0.f : __expf(sc[nt][1]);
                float e2 = (gr1 == gc)     ? 0.f : __expf(sc[nt][2]);
                float e3 = (gr1 == gc + 1) ? 0.f : __expf(sc[nt][3]);
                sc[nt][0] = e0; sc[nt][1] = e1; sc[nt][2] = e2; sc[nt][3] = e3;
                rs0 += e0 + e1; rs1 += e2 + e3;
            }
        } else {
            #pragma unroll
            for (int nt = 0; nt < 16; nt++) {
                float e0 = __expf(sc[nt][0]);
                float e1 = __expf(sc[nt][1]);
                float e2 = __expf(sc[nt][2]);
                float e3 = __expf(sc[nt][3]);
                sc[nt][0] = e0; sc[nt][1] = e1; sc[nt][2] = e2; sc[nt][3] = e3;
                rs0 += e0 + e1; rs1 += e2 + e3;
            }
        }
        rs0 += __shfl_xor_sync(0xffffffffu, rs0, 1);
        rs0 += __shfl_xor_sync(0xffffffffu, rs0, 2);
        rs1 += __shfl_xor_sync(0xffffffffu, rs1, 1);
        rs1 += __shfl_xor_sync(0xffffffffu, rs1, 2);
        l0 += rs0; l1 += rs1;

        CP_WAIT(0);
        __syncthreads();

        if (more) {
            ld_tile_async(sb + AK0, g_kb0 + (size_t)(kofs + kb + 128) * CC, tid);
            ld_tile_async(sb + AK1, g_kb1 + (size_t)(kofs + kb + 128) * CC, tid);
            CP_COMMIT();
        }

        #pragma unroll
        for (int kc = 0; kc < 8; kc++) {
            uint32_t p0[4], p1[4];
            split_pair_h(sc[2 * kc][0],     sc[2 * kc][1],     p0[0], p1[0]);
            split_pair_h(sc[2 * kc][2],     sc[2 * kc][3],     p0[1], p1[1]);
            split_pair_h(sc[2 * kc + 1][0], sc[2 * kc + 1][1], p0[2], p1[2]);
            split_pair_h(sc[2 * kc + 1][2], sc[2 * kc + 1][3], p0[3], p1[3]);
            #pragma unroll
            for (int nt2 = 0; nt2 < 8; nt2++) {
                uint32_t vf[4];
                ldsm4t(vf, sb + AV0 + (uint32_t)(kc * 16 * 272) + voff + nt2 * 32);
                mma16816h(pv[2 * nt2],     p0, vf[0], vf[1]);
                mma16816h(pv[2 * nt2 + 1], p0, vf[2], vf[3]);
                mma16816h(pv[2 * nt2],     p1, vf[0], vf[1]);
                mma16816h(pv[2 * nt2 + 1], p1, vf[2], vf[3]);
            }
        }
        __syncthreads();

        if (more) {
            ld_tile_async(sb + AV0, g_vh + (size_t)(kofs + kb + 128) * CC, tid);
            CP_COMMIT();
            CP_WAIT(1);
            __syncthreads();
        }
    }

    float* aout = g_acc + (size_t)blockIdx.y * NN * CC;
    #pragma unroll
    for (int nt = 0; nt < 16; nt++) {
        int c = nt * 8 + qc;
        *reinterpret_cast<float2*>(aout + (size_t)gr0 * CC + c) = make_float2(pv[nt][0], pv[nt][1]);
        *reinterpret_cast<float2*>(aout + (size_t)gr1 * CC + c) = make_float2(pv[nt][2], pv[nt][3]);
    }
    if ((lane & 3) == 0) {
        g_l[blockIdx.y * NN + gr0] = l0;
        g_l[blockIdx.y * NN + gr1] = l1;
    }
}

// ---------------- K3: fused combine + norm + bf16 split ----------------
__global__ __launch_bounds__(256) void combine_norm_kernel()
{
    int row  = blockIdx.x * 8 + (threadIdx.x >> 5);
    int lane = threadIdx.x & 31;
    size_t base = (size_t)row * CC + lane * 4;

    float inv = __fdividef(1.f, g_l[row] + g_l[NN + row]);
    float4 a0 = *reinterpret_cast<const float4*>(g_acc + base);
    float4 a1 = *reinterpret_cast<const float4*>(g_acc + NN * CC + base);
    float4 sk = *reinterpret_cast<const float4*>(g_skip + base);

    float4 h;
    h.x = (a0.x + a1.x) * inv + sk.x;
    h.y = (a0.y + a1.y) * inv + sk.y;
    h.z = (a0.z + a1.z) * inv + sk.z;
    h.w = (a0.w + a1.w) * inv + sk.w;
    *reinterpret_cast<float4*>(g_h + base) = h;

    uint2 hb = {pack_bf(h.x, h.y), pack_bf(h.z, h.w)};
    *reinterpret_cast<uint2*>(g_hb0 + base) = hb;

    float s = h.x * h.x + h.y * h.y + h.z * h.z + h.w * h.w;
    s += __shfl_xor_sync(0xffffffffu, s, 16);
    s += __shfl_xor_sync(0xffffffffu, s, 8);
    s += __shfl_xor_sync(0xffffffffu, s, 4);
    s += __shfl_xor_sync(0xffffffffu, s, 2);
    s += __shfl_xor_sync(0xffffffffu, s, 1);
    if (lane == 0) g_norm[row] = 0.5f * s;
}

// ---------------- K4: kNN candidates — two-phase selection, zero-C mma ----------------
#define KQ0 0
#define KKA 34816
#define KKB 69632
#define KNR 104448         // 2 x 128 f32
#define KNN_SMEM 105472

__global__ __launch_bounds__(256, 1) void knn_mma_kernel()
{
    extern __shared__ __align__(16) char smc[];
    const uint32_t sb = smem_u32(smc);
    float* nr_all = reinterpret_cast<float*>(smc + KNR);

    const int tid  = threadIdx.x, wid = tid >> 5, lane = tid & 31;
    const int qbase = blockIdx.x * 128;
    const int kofs  = blockIdx.y * HALFN;

    ld_tile_async(sb + KQ0, g_hb0 + (size_t)qbase * CC, tid);
    CP_COMMIT();
    ld_tile_async(sb + KKA, g_hb0 + (size_t)kofs * CC, tid);
    CP_COMMIT();
    if (tid < 128) nr_all[tid] = g_norm[kofs + tid];

    const int r0   = wid * 16;
    const int qrow = lane >> 2, qc = (lane & 3) * 2;
    const int gr0  = qbase + r0 + qrow, gr1 = gr0 + 8;
    const int lr0  = r0 + qrow, lr1 = lr0 + 8;
    const int slot = lane & 3;

    const uint32_t aoff = (uint32_t)((r0 + (lane & 15)) * 272 + ((lane >> 4) & 1) * 16);
    const uint32_t boff = (uint32_t)(((lane & 7) + ((lane >> 4) & 1) * 8) * 272 + ((lane >> 3) & 1) * 16);

    float tv0[8], tv1[8];
    int   ti0[8], ti1[8];
    #pragma unroll
    for (int t = 0; t < 8; t++) { tv0[t] = -3e38f; tv1[t] = -3e38f; ti0[t] = 0; ti1[t] = 0; }
    float vmin0 = -3e38f, vmin1 = -3e38f;

    int buf = 0;
    for (int t = 0; t < NT; t++) {
        if (t + 1 < NT) {
            ld_tile_async(sb + KKA + (uint32_t)((buf ^ 1) * 34816),
                          g_hb0 + (size_t)(kofs + (t + 1) * 128) * CC, tid);
            CP_COMMIT();
            if (tid < 128) nr_all[(buf ^ 1) * 128 + tid] = g_norm[kofs + (t + 1) * 128 + tid];
            CP_WAIT(1);
        } else {
            CP_WAIT(0);
        }
        __syncthreads();

        const uint32_t kbase = sb + KKA + (uint32_t)(buf * 34816);
        const float* nr_s = nr_all + buf * 128;

        float sc[16][4];

        #pragma unroll
        for (int kc = 0; kc < 8; kc++) {
            uint32_t a[4];
            ldsm4(a, sb + KQ0 + aoff + kc * 32);
            if (kc == 0) {
                #pragma unroll
                for (int nt2 = 0; nt2 < 8; nt2++) {
                    uint32_t b[4];
                    ldsm4(b, kbase + (uint32_t)(nt2 * 16 * 272) + boff);
                    mma16816z(sc[2 * nt2],     a, b[0], b[1]);
                    mma16816z(sc[2 * nt2 + 1], a, b[2], b[3]);
                }
            } else {
                #pragma unroll
                for (int nt2 = 0; nt2 < 8; nt2++) {
                    uint32_t b[4];
                    ldsm4(b, kbase + (uint32_t)(nt2 * 16 * 272) + boff + kc * 32);
                    mma16816(sc[2 * nt2],     a, b[0], b[1]);
                    mma16816(sc[2 * nt2 + 1], a, b[2], b[3]);
                }
            }
        }

        const int kb = t * 128;

        // phase 1: adjust in place, mask diag (uniform rare branch), row maxes
        #pragma unroll
        for (int nt = 0; nt < 16; nt++) {
            int c = nt * 8 + qc;
            float nr0 = nr_s[c], nr1 = nr_s[c + 1];
            sc[nt][0] -= nr0;
            sc[nt][1] -= nr1;
            sc[nt][2] -= nr0;
            sc[nt][3] -= nr1;
        }
        if (kofs + kb == qbase) {
            #pragma unroll
            for (int nt = 0; nt < 16; nt++) {
                int gc = kofs + kb + nt * 8 + qc;
                if (gr0 == gc)     sc[nt][0] = -3e38f;
                if (gr0 == gc + 1) sc[nt][1] = -3e38f;
                if (gr1 == gc)     sc[nt][2] = -3e38f;
                if (gr1 == gc + 1) sc[nt][3] = -3e38f;
            }
        }
        float m0 = -3e38f, m1 = -3e38f;
        #pragma unroll
        for (int nt = 0; nt < 16; nt++) {
            m0 = fmaxf(m0, fmaxf(sc[nt][0], sc[nt][1]));
            m1 = fmaxf(m1, fmaxf(sc[nt][2], sc[nt][3]));
        }

        // phase 2: rare insert-scan per row
        if (m0 > vmin0) {
            #pragma unroll
            for (int nt = 0; nt < 16; nt++) {
                int gc = kofs + kb + nt * 8 + qc;
                if (sc[nt][0] > vmin0) { ins8(tv0, ti0, sc[nt][0], gc);     vmin0 = tv0[7]; }
                if (sc[nt][1] > vmin0) { ins8(tv0, ti0, sc[nt][1], gc + 1); vmin0 = tv0[7]; }
            }
        }
        if (m1 > vmin1) {
            #pragma unroll
            for (int nt = 0; nt < 16; nt++) {
                int gc = kofs + kb + nt * 8 + qc;
                if (sc[nt][2] > vmin1) { ins8(tv1, ti1, sc[nt][2], gc);     vmin1 = tv1[7]; }
                if (sc[nt][3] > vmin1) { ins8(tv1, ti1, sc[nt][3], gc + 1); vmin1 = tv1[7]; }
            }
        }
        __syncthreads();
        buf ^= 1;
    }

    // merge: 4 threads x 8 entries per row -> smem -> top-16 per row
    float* mv = reinterpret_cast<float*>(smc);            // [128][32]
    int*   mi = reinterpret_cast<int*>(smc + 16384);      // [128][32]
    #pragma unroll
    for (int t = 0; t < 8; t++) {
        mv[lr0 * 32 + slot * 8 + t] = tv0[t];
        mi[lr0 * 32 + slot * 8 + t] = ti0[t];
        mv[lr1 * 32 + slot * 8 + t] = tv1[t];
        mi[lr1 * 32 + slot * 8 + t] = ti1[t];
    }
    __syncthreads();

    if (tid < 128) {
        const float* rv = mv + tid * 32;
        const int*   ri = mi + tid * 32;
        float bv[NCAND]; int bi[NCAND];
        #pragma unroll
        for (int t = 0; t < NCAND; t++) { bv[t] = -3e38f; bi[t] = 0; }
        float vm = -3e38f;
        #pragma unroll 4
        for (int j = 0; j < 32; j++) {
            float v = rv[j];
            if (v > vm) {
                float cv = v; int ci2 = ri[j];
                #pragma unroll
                for (int t = 0; t < NCAND; t++) {
                    if (cv > bv[t]) {
                        float a = bv[t]; bv[t] = cv; cv = a;
                        int   b = bi[t]; bi[t] = ci2; ci2 = b;
                    }
                }
                vm = bv[NCAND - 1];
            }
        }
        float* outv = g_cv16 + (size_t)blockIdx.y * NN * NCAND + (size_t)(qbase + tid) * NCAND;
        int*   outi = g_ci16 + (size_t)blockIdx.y * NN * NCAND + (size_t)(qbase + tid) * NCAND;
        #pragma unroll
        for (int t = 0; t < NCAND; t++) { outv[t] = bv[t]; outi[t] = bi[t]; }
    }
}

// ---------------- K5: exact fp32 rescore of 32 candidates -> top-7 ----------------
__global__ __launch_bounds__(256) void knn_rescore_kernel()
{
    int node = (blockIdx.x * 256 + threadIdx.x) >> 5;
    int lane = threadIdx.x & 31;

    float4 hv = *reinterpret_cast<const float4*>(g_h + (size_t)node * CC + lane * 4);
    int half = lane >> 4, slot = lane & 15;
    int ci = g_ci16[(size_t)half * NN * NCAND + (size_t)node * NCAND + slot];

    float myv = -3e38f;
    for (int c = 0; c < 32; c++) {
        int cj = __shfl_sync(0xffffffffu, ci, c);
        float4 hc = *reinterpret_cast<const float4*>(g_h + (size_t)cj * CC + lane * 4);
        float p = hv.x * hc.x + hv.y * hc.y + hv.z * hc.z + hv.w * hc.w;
        #pragma unroll
        for (int m = 16; m >= 1; m >>= 1) p += __shfl_xor_sync(0xffffffffu, p, m);
        if (lane == c) myv = p - g_norm[cj];
    }

    float v = myv; int idx = ci;
    #pragma unroll
    for (int t = 0; t < KNBR; t++) {
        float bv = v; int bidx = idx;
        #pragma unroll
        for (int m = 16; m >= 1; m >>= 1) {
            float ov = __shfl_xor_sync(0xffffffffu, bv, m);
            int   oi = __shfl_xor_sync(0xffffffffu, bidx, m);
            if (ov > bv || (ov == bv && oi < bidx)) { bv = ov; bidx = oi; }
        }
        if (lane == 0) g_idx[node * KNBR + t] = bidx;
        if (idx == bidx) v = -3.3e38f;
    }
}

// ---------------- K6: m1 = h @ W1 ----------------
__global__ __launch_bounds__(256) void gcn1_gemm(const float* __restrict__ W1)
{
    __shared__ float xs[32 * 129];
    const int tid = threadIdx.x;
    const int r0  = blockIdx.x * 32;

    for (int i = tid; i < 32 * CC; i += 256) {
        int r = i >> 7, c = i & 127;
        xs[r * 129 + c] = g_h[(r0 + r) * CC + c];
    }
    __syncthreads();

    const int ri = (tid >> 5) * 4;
    const int c0 = (tid & 31) * 4;

    ull acc[4][2];
    #pragma unroll
    for (int i = 0; i < 4; i++) { acc[i][0] = 0ULL; acc[i][1] = 0ULL; }

    #pragma unroll 4
    for (int k2 = 0; k2 < CC; k2++) {
        ulonglong2 wp = *reinterpret_cast<const ulonglong2*>(W1 + k2 * CC + c0);
        #pragma unroll
        for (int dr = 0; dr < 4; dr++) {
            ull x2 = dup2(xs[(ri + dr) * 129 + k2]);
            acc[dr][0] = ffma2(x2, wp.x, acc[dr][0]);
            acc[dr][1] = ffma2(x2, wp.y, acc[dr][1]);
        }
    }
    #pragma unroll
    for (int dr = 0; dr < 4; dr++) {
        float2 a0 = upk(acc[dr][0]), a1 = upk(acc[dr][1]);
        float4 o = {a0.x, a0.y, a1.x, a1.y};
        *reinterpret_cast<float4*>(g_m1 + (r0 + ri + dr) * CC + c0) = o;
    }
}

// ---------------- K7: GCN layer-1 gather + relu ----------------
__global__ __launch_bounds__(128) void gather1(const float* __restrict__ b1)
{
    int node = blockIdx.x;
    int c    = threadIdx.x;
    float s = g_m1[node * CC + c];
    #pragma unroll
    for (int t = 0; t < KNBR; t++) {
        int nb = g_idx[node * KNBR + t];
        s += g_m1[nb * CC + c];
    }
    g_h1[node * CC + c] = fmaxf(s * 0.125f + b1[c], 0.f);
}

// ---------------- K8: m2 = h1 @ W2 ----------------
__global__ __launch_bounds__(256) void m2_kernel(const float* __restrict__ W2)
{
    int row  = blockIdx.x * 8 + (threadIdx.x >> 5);
    int lane = threadIdx.x & 31;
    float s = 0.f;
    for (int c = lane; c < CC; c += 32) s += g_h1[row * CC + c] * W2[c];
    s += __shfl_xor_sync(0xffffffffu, s, 16);
    s += __shfl_xor_sync(0xffffffffu, s, 8);
    s += __shfl_xor_sync(0xffffffffu, s, 4);
    s += __shfl_xor_sync(0xffffffffu, s, 2);
    s += __shfl_xor_sync(0xffffffffu, s, 1);
    if (lane == 0) g_m2[row] = s;
}

// ---------------- K9: GCN layer-2 gather -> output ----------------
__global__ __launch_bounds__(256) void out_kernel(const float* __restrict__ b2,
                                                  float* __restrict__ out)
{
    int n = blockIdx.x * 256 + threadIdx.x;
    float s = g_m2[n];
    #pragma unroll
    for (int t = 0; t < KNBR; t++) s += g_m2[g_idx[n * KNBR + t]];
    out[n] = s * 0.125f + b2[0];
}

// ---------------- launch ----------------
extern "C" void kernel_launch(void* const* d_in, const int* in_sizes, int n_in,
                              void* d_out, int out_size)
{
    const float* x   = (const float*)d_in[0];
    const float* Wq  = (const float*)d_in[1];
    const float* bq  = (const float*)d_in[2];
    const float* Wk  = (const float*)d_in[3];
    const float* bk  = (const float*)d_in[4];
    const float* Wv  = (const float*)d_in[5];
    const float* bv  = (const float*)d_in[6];
    const float* Wsk = (const float*)d_in[7];
    const float* bsk = (const float*)d_in[8];
    const float* W1  = (const float*)d_in[9];
    const float* b1  = (const float*)d_in[10];
    const float* W2  = (const float*)d_in[11];
    const float* b2  = (const float*)d_in[12];
    float* out = (float*)d_out;

    cudaFuncSetAttribute(attn_mma_kernel, cudaFuncAttributeMaxDynamicSharedMemorySize, ATTN_SMEM);
    cudaFuncSetAttribute(knn_mma_kernel,  cudaFuncAttributeMaxDynamicSharedMemorySize, KNN_SMEM);

    proj_kernel<<<NN / 32, 256>>>(x, Wq, bq, Wk, bk, Wv, bv, Wsk, bsk);
    attn_mma_kernel<<<dim3(NN / 128, 2), 256, ATTN_SMEM>>>();
    combine_norm_kernel<<<NN / 8, 256>>>();
    knn_mma_kernel<<<dim3(NN / 128, 2), 256, KNN_SMEM>>>();
    knn_rescore_kernel<<<NN / 8, 256>>>();
    gcn1_gemm<<<NN / 32, 256>>>(W1);
    gather1<<<NN, CC>>>(b1);
    m2_kernel<<<NN / 8, 256>>>(W2);
    out_kernel<<<NN / 256, 256>>>(b2, out);
}

// round 10
// speedup vs baseline: 1.0938x; 1.0938x over previous
#include <cuda_runtime.h>
#include <cuda_bf16.h>
#include <cuda_fp16.h>
#include <cstdint>

#define NN    8192
#define CC    128
#define KNBR  7
#define HALFN 4096
#define QUARTN 2048
#define NTQ   (QUARTN / 128)
#define NT    (HALFN / 128)
#define NCQ   8

typedef unsigned long long ull;

// ---------------- device scratch ----------------
__device__ float g_skip[NN * CC];
__device__ float g_h[NN * CC];
__device__ float g_acc[2 * NN * CC];
__device__ float g_l[2 * NN];
__device__ float g_norm[NN];
__device__ int   g_ci8[4 * NN * NCQ];   // per-quarter top-8 candidate indices
__device__ int   g_idx[NN * KNBR];
__device__ float g_m1[NN * CC];
__device__ float g_h1[NN * CC];
__device__ float g_m2[NN];
__device__ __nv_bfloat16 g_qb0[NN * CC], g_qb1[NN * CC];
__device__ __nv_bfloat16 g_kb0[NN * CC], g_kb1[NN * CC];
__device__ __half        g_vh[NN * CC];
__device__ __nv_bfloat16 g_hb0[NN * CC];

// ---------------- packed fp32x2 (SIMT GEMMs) ----------------
__device__ __forceinline__ ull ffma2(ull a, ull b, ull c) {
    ull d;
    asm("fma.rn.f32x2 %0, %1, %2, %3;" : "=l"(d) : "l"(a), "l"(b), "l"(c));
    return d;
}
__device__ __forceinline__ ull dup2(float x) {
    ull d;
    asm("mov.b64 %0, {%1, %1};" : "=l"(d) : "f"(x));
    return d;
}
__device__ __forceinline__ float2 upk(ull v) {
    float2 r;
    asm("mov.b64 {%0, %1}, %2;" : "=f"(r.x), "=f"(r.y) : "l"(v));
    return r;
}

// ---------------- mma / ldmatrix / cp.async helpers ----------------
__device__ __forceinline__ uint32_t smem_u32(const void* p) {
    uint32_t a;
    asm("{ .reg .u64 t; cvta.to.shared.u64 t, %1; cvt.u32.u64 %0, t; }" : "=r"(a) : "l"(p));
    return a;
}
__device__ __forceinline__ void ldsm4(uint32_t* r, uint32_t a) {
    asm volatile("ldmatrix.sync.aligned.m8n8.x4.shared.b16 {%0,%1,%2,%3}, [%4];"
                 : "=r"(r[0]), "=r"(r[1]), "=r"(r[2]), "=r"(r[3]) : "r"(a));
}
__device__ __forceinline__ void ldsm4t(uint32_t* r, uint32_t a) {
    asm volatile("ldmatrix.sync.aligned.m8n8.x4.trans.shared.b16 {%0,%1,%2,%3}, [%4];"
                 : "=r"(r[0]), "=r"(r[1]), "=r"(r[2]), "=r"(r[3]) : "r"(a));
}
__device__ __forceinline__ void mma16816(float* c, const uint32_t* a, uint32_t b0, uint32_t b1) {
    asm volatile(
        "mma.sync.aligned.m16n8k16.row.col.f32.bf16.bf16.f32 "
        "{%0,%1,%2,%3}, {%4,%5,%6,%7}, {%8,%9}, {%0,%1,%2,%3};"
        : "+f"(c[0]), "+f"(c[1]), "+f"(c[2]), "+f"(c[3])
        : "r"(a[0]), "r"(a[1]), "r"(a[2]), "r"(a[3]), "r"(b0), "r"(b1));
}
// first-touch variant: d = a*b + 0
__device__ __forceinline__ void mma16816z(float* d, const uint32_t* a, uint32_t b0, uint32_t b1) {
    asm volatile(
        "mma.sync.aligned.m16n8k16.row.col.f32.bf16.bf16.f32 "
        "{%0,%1,%2,%3}, {%4,%5,%6,%7}, {%8,%9}, {%10,%10,%10,%10};"
        : "=f"(d[0]), "=f"(d[1]), "=f"(d[2]), "=f"(d[3])
        : "r"(a[0]), "r"(a[1]), "r"(a[2]), "r"(a[3]), "r"(b0), "r"(b1), "f"(0.f));
}
__device__ __forceinline__ void mma16816h(float* c, const uint32_t* a, uint32_t b0, uint32_t b1) {
    asm volatile(
        "mma.sync.aligned.m16n8k16.row.col.f32.f16.f16.f32 "
        "{%0,%1,%2,%3}, {%4,%5,%6,%7}, {%8,%9}, {%0,%1,%2,%3};"
        : "+f"(c[0]), "+f"(c[1]), "+f"(c[2]), "+f"(c[3])
        : "r"(a[0]), "r"(a[1]), "r"(a[2]), "r"(a[3]), "r"(b0), "r"(b1));
}
#define CP_COMMIT() asm volatile("cp.async.commit_group;" ::: "memory")
#define CP_WAIT(n)  asm volatile("cp.async.wait_group %0;" :: "n"(n) : "memory")

__device__ __forceinline__ uint32_t pack_bf(float x, float y) {
    __nv_bfloat162 t = __floats2bfloat162_rn(x, y);
    return *reinterpret_cast<uint32_t*>(&t);
}
__device__ __forceinline__ uint32_t pack_h(float x, float y) {
    __half2 t = __floats2half2_rn(x, y);
    return *reinterpret_cast<uint32_t*>(&t);
}
__device__ __forceinline__ void split_pair(float x, float y, uint32_t& p0, uint32_t& p1) {
    __nv_bfloat16 bx = __float2bfloat16_rn(x), by = __float2bfloat16_rn(y);
    __nv_bfloat162 t; t.x = bx; t.y = by;
    p0 = *reinterpret_cast<uint32_t*>(&t);
    p1 = pack_bf(x - __bfloat162float(bx), y - __bfloat162float(by));
}
__device__ __forceinline__ void split_pair_h(float x, float y, uint32_t& p0, uint32_t& p1) {
    __half hx = __float2half_rn(x), hy = __float2half_rn(y);
    __half2 t; t.x = hx; t.y = hy;
    p0 = *reinterpret_cast<uint32_t*>(&t);
    p1 = pack_h(x - __half2float(hx), y - __half2float(hy));
}
// async 128x128 16-bit tile -> smem rows of 272B
__device__ __forceinline__ void ld_tile_async(uint32_t dst, const void* __restrict__ srcv, int tid) {
    const char* src = reinterpret_cast<const char*>(srcv);
    #pragma unroll
    for (int i = 0; i < 8; i++) {
        int idx = tid + i * 256;
        int row = idx >> 4, ch = idx & 15;
        asm volatile("cp.async.cg.shared.global [%0], [%1], 16;" ::
            "r"(dst + (uint32_t)(row * 272 + ch * 16)), "l"(src + (size_t)row * CC * 2 + ch * 16) : "memory");
    }
}
// register top-8 insert
__device__ __forceinline__ void ins8(float* tv, int* ti, float v, int idx) {
    #pragma unroll
    for (int t = 0; t < 8; t++) {
        if (v > tv[t]) {
            float a = tv[t]; tv[t] = v; v = a;
            int   b = ti[t]; ti[t] = idx; idx = b;
        }
    }
}

// ---------------- K1: fused projections -> bf16 splits (q,k), fp16 (v), skip ----------------
__global__ __launch_bounds__(256) void proj_kernel(
    const float* __restrict__ x,
    const float* __restrict__ Wq, const float* __restrict__ bq,
    const float* __restrict__ Wk, const float* __restrict__ bk,
    const float* __restrict__ Wv, const float* __restrict__ bv,
    const float* __restrict__ Ws, const float* __restrict__ bs)
{
    __shared__ float xs[32 * 129];
    const int tid = threadIdx.x;
    const int r0  = blockIdx.x * 32;
    const float SCALE = 0.08838834764831843f;

    for (int i = tid; i < 32 * CC; i += 256) {
        int r = i >> 7, c = i & 127;
        xs[r * 129 + c] = x[(r0 + r) * CC + c];
    }
    __syncthreads();

    const int ri = (tid >> 5) * 4;
    const int c0 = (tid & 31) * 4;

    const float* Wt[4] = {Wq, Wk, Wv, Ws};
    const float* bt[4] = {bq, bk, bv, bs};

    #pragma unroll
    for (int w = 0; w < 4; w++) {
        const float* W = Wt[w];
        ull acc[4][2];
        #pragma unroll
        for (int i = 0; i < 4; i++) { acc[i][0] = 0ULL; acc[i][1] = 0ULL; }

        #pragma unroll 4
        for (int k2 = 0; k2 < CC; k2++) {
            ulonglong2 wp = *reinterpret_cast<const ulonglong2*>(W + k2 * CC + c0);
            #pragma unroll
            for (int dr = 0; dr < 4; dr++) {
                ull x2 = dup2(xs[(ri + dr) * 129 + k2]);
                acc[dr][0] = ffma2(x2, wp.x, acc[dr][0]);
                acc[dr][1] = ffma2(x2, wp.y, acc[dr][1]);
            }
        }
        float4 bb = *reinterpret_cast<const float4*>(bt[w] + c0);
        #pragma unroll
        for (int dr = 0; dr < 4; dr++) {
            float2 a0 = upk(acc[dr][0]), a1 = upk(acc[dr][1]);
            int row = r0 + ri + dr;
            float ox = a0.x + bb.x, oy = a0.y + bb.y;
            float oz = a1.x + bb.z, ow = a1.y + bb.w;
            if (w == 3) {
                float4 o = {ox, oy, oz, ow};
                *reinterpret_cast<float4*>(g_skip + row * CC + c0) = o;
            } else if (w == 2) {
                uint2 u = {pack_h(ox, oy), pack_h(oz, ow)};
                *reinterpret_cast<uint2*>(g_vh + row * CC + c0) = u;
            } else {
                float s = (w == 0) ? SCALE : 1.f;
                ox *= s; oy *= s; oz *= s; ow *= s;
                uint32_t lo0, hi0, lo1, hi1;
                split_pair(ox, oy, lo0, hi0);
                split_pair(oz, ow, lo1, hi1);
                __nv_bfloat16* d0 = (w == 0) ? g_qb0 : g_kb0;
                __nv_bfloat16* d1 = (w == 0) ? g_qb1 : g_kb1;
                uint2 u0 = {lo0, lo1};
                uint2 u1 = {hi0, hi1};
                *reinterpret_cast<uint2*>(d0 + row * CC + c0) = u0;
                *reinterpret_cast<uint2*>(d1 + row * CC + c0) = u1;
            }
        }
    }
}

// ---------------- K2: flash attention, pipelined (unchanged from R9) ----------------
#define AQ0 0
#define AQ1 34816
#define AK0 69632
#define AK1 104448
#define AV0 139264
#define ATTN_SMEM 174080

__global__ __launch_bounds__(256, 1) void attn_mma_kernel()
{
    extern __shared__ __align__(16) char smc[];
    const uint32_t sb = smem_u32(smc);
    const int tid  = threadIdx.x, wid = tid >> 5, lane = tid & 31;
    const int qbase = blockIdx.x * 128;
    const int kofs  = blockIdx.y * HALFN;

    ld_tile_async(sb + AQ0, g_qb0 + (size_t)qbase * CC, tid);
    ld_tile_async(sb + AQ1, g_qb1 + (size_t)qbase * CC, tid);
    CP_COMMIT();
    ld_tile_async(sb + AK0, g_kb0 + (size_t)kofs * CC, tid);
    ld_tile_async(sb + AK1, g_kb1 + (size_t)kofs * CC, tid);
    CP_COMMIT();
    ld_tile_async(sb + AV0, g_vh + (size_t)kofs * CC, tid);
    CP_COMMIT();

    const int r0   = wid * 16;
    const int qrow = lane >> 2, qc = (lane & 3) * 2;
    const int gr0  = qbase + r0 + qrow, gr1 = gr0 + 8;

    const uint32_t aoff = (uint32_t)((r0 + (lane & 15)) * 272 + ((lane >> 4) & 1) * 16);
    const uint32_t boff = (uint32_t)(((lane & 7) + ((lane >> 4) & 1) * 8) * 272 + ((lane >> 3) & 1) * 16);
    const uint32_t voff = (uint32_t)(((lane & 7) + ((lane >> 3) & 1) * 8) * 272 + ((lane >> 4) & 1) * 16);

    float pv[16][4];
    #pragma unroll
    for (int i = 0; i < 16; i++)
        #pragma unroll
        for (int j = 0; j < 4; j++) pv[i][j] = 0.f;
    float l0 = 0.f, l1 = 0.f;

    CP_WAIT(1);
    __syncthreads();

    for (int t = 0; t < NT; t++) {
        const int kb = t * 128;
        const bool more = (t + 1 < NT);

        float sc[16][4];

        #pragma unroll
        for (int kc = 0; kc < 8; kc++) {
            uint32_t a0[4], a1[4];
            ldsm4(a0, sb + AQ0 + aoff + kc * 32);
            ldsm4(a1, sb + AQ1 + aoff + kc * 32);
            if (kc == 0) {
                #pragma unroll
                for (int nt2 = 0; nt2 < 8; nt2++) {
                    uint32_t b[4];
                    ldsm4(b, sb + AK0 + (uint32_t)(nt2 * 16 * 272) + boff);
                    mma16816z(sc[2 * nt2],     a0, b[0], b[1]);
                    mma16816z(sc[2 * nt2 + 1], a0, b[2], b[3]);
                    mma16816(sc[2 * nt2],     a1, b[0], b[1]);
                    mma16816(sc[2 * nt2 + 1], a1, b[2], b[3]);
                }
            } else {
                #pragma unroll
                for (int nt2 = 0; nt2 < 8; nt2++) {
                    uint32_t b[4];
                    ldsm4(b, sb + AK0 + (uint32_t)(nt2 * 16 * 272) + boff + kc * 32);
                    mma16816(sc[2 * nt2],     a0, b[0], b[1]);
                    mma16816(sc[2 * nt2 + 1], a0, b[2], b[3]);
                    mma16816(sc[2 * nt2],     a1, b[0], b[1]);
                    mma16816(sc[2 * nt2 + 1], a1, b[2], b[3]);
                }
            }
            #pragma unroll
            for (int nt2 = 0; nt2 < 8; nt2++) {
                uint32_t b[4];
                ldsm4(b, sb + AK1 + (uint32_t)(nt2 * 16 * 272) + boff + kc * 32);
                mma16816(sc[2 * nt2],     a0, b[0], b[1]);
                mma16816(sc[2 * nt2 + 1], a0, b[2], b[3]);
            }
        }

        float rs0 = 0.f, rs1 = 0.f;
        if (kofs + kb == qbase) {
            #pragma unroll
            for (int nt = 0; nt < 16; nt++) {
                int gc = kofs + kb + nt * 8 + qc;
                float e0 = (gr0 == gc)     ? 0.f : __expf(sc[nt][0]);
                float e1 = (gr0 == gc + 1) ? 0.f : __expf(sc[nt][1]);
                float e2 = (gr1 == gc)     ? 0.f : __expf(sc[nt][2]);
                float e3 = (gr1 == gc + 1) ? 0.f : __expf(sc[nt][3]);
                sc[nt][0] = e0; sc[nt][1] = e1; sc[nt][2] = e2; sc[nt][3] = e3;
                rs0 += e0 + e1; rs1 += e2 + e3;
            }
        } else {
            #pragma unroll
            for (int nt = 0; nt < 16; nt++) {
                float e0 = __expf(sc[nt][0]);
                float e1 = __expf(sc[nt][1]);
                float e2 = __expf(sc[nt][2]);
                float e3 = __expf(sc[nt][3]);
                sc[nt][0] = e0; sc[nt][1] = e1; sc[nt][2] = e2; sc[nt][3] = e3;
                rs0 += e0 + e1; rs1 += e2 + e3;
            }
        }
        rs0 += __shfl_xor_sync(0xffffffffu, rs0, 1);
        rs0 += __shfl_xor_sync(0xffffffffu, rs0, 2);
        rs1 += __shfl_xor_sync(0xffffffffu, rs1, 1);
        rs1 += __shfl_xor_sync(0xffffffffu, rs1, 2);
        l0 += rs0; l1 += rs1;

        CP_WAIT(0);
        __syncthreads();

        if (more) {
            ld_tile_async(sb + AK0, g_kb0 + (size_t)(kofs + kb + 128) * CC, tid);
            ld_tile_async(sb + AK1, g_kb1 + (size_t)(kofs + kb + 128) * CC, tid);
            CP_COMMIT();
        }

        #pragma unroll
        for (int kc = 0; kc < 8; kc++) {
            uint32_t p0[4], p1[4];
            split_pair_h(sc[2 * kc][0],     sc[2 * kc][1],     p0[0], p1[0]);
            split_pair_h(sc[2 * kc][2],     sc[2 * kc][3],     p0[1], p1[1]);
            split_pair_h(sc[2 * kc + 1][0], sc[2 * kc + 1][1], p0[2], p1[2]);
            split_pair_h(sc[2 * kc + 1][2], sc[2 * kc + 1][3], p0[3], p1[3]);
            #pragma unroll
            for (int nt2 = 0; nt2 < 8; nt2++) {
                uint32_t vf[4];
                ldsm4t(vf, sb + AV0 + (uint32_t)(kc * 16 * 272) + voff + nt2 * 32);
                mma16816h(pv[2 * nt2],     p0, vf[0], vf[1]);
                mma16816h(pv[2 * nt2 + 1], p0, vf[2], vf[3]);
                mma16816h(pv[2 * nt2],     p1, vf[0], vf[1]);
                mma16816h(pv[2 * nt2 + 1], p1, vf[2], vf[3]);
            }
        }
        __syncthreads();

        if (more) {
            ld_tile_async(sb + AV0, g_vh + (size_t)(kofs + kb + 128) * CC, tid);
            CP_COMMIT();
            CP_WAIT(1);
            __syncthreads();
        }
    }

    float* aout = g_acc + (size_t)blockIdx.y * NN * CC;
    #pragma unroll
    for (int nt = 0; nt < 16; nt++) {
        int c = nt * 8 + qc;
        *reinterpret_cast<float2*>(aout + (size_t)gr0 * CC + c) = make_float2(pv[nt][0], pv[nt][1]);
        *reinterpret_cast<float2*>(aout + (size_t)gr1 * CC + c) = make_float2(pv[nt][2], pv[nt][3]);
    }
    if ((lane & 3) == 0) {
        g_l[blockIdx.y * NN + gr0] = l0;
        g_l[blockIdx.y * NN + gr1] = l1;
    }
}

// ---------------- K3: fused combine + norm + bf16 split ----------------
__global__ __launch_bounds__(256) void combine_norm_kernel()
{
    int row  = blockIdx.x * 8 + (threadIdx.x >> 5);
    int lane = threadIdx.x & 31;
    size_t base = (size_t)row * CC + lane * 4;

    float inv = __fdividef(1.f, g_l[row] + g_l[NN + row]);
    float4 a0 = *reinterpret_cast<const float4*>(g_acc + base);
    float4 a1 = *reinterpret_cast<const float4*>(g_acc + NN * CC + base);
    float4 sk = *reinterpret_cast<const float4*>(g_skip + base);

    float4 h;
    h.x = (a0.x + a1.x) * inv + sk.x;
    h.y = (a0.y + a1.y) * inv + sk.y;
    h.z = (a0.z + a1.z) * inv + sk.z;
    h.w = (a0.w + a1.w) * inv + sk.w;
    *reinterpret_cast<float4*>(g_h + base) = h;

    uint2 hb = {pack_bf(h.x, h.y), pack_bf(h.z, h.w)};
    *reinterpret_cast<uint2*>(g_hb0 + base) = hb;

    float s = h.x * h.x + h.y * h.y + h.z * h.z + h.w * h.w;
    s += __shfl_xor_sync(0xffffffffu, s, 16);
    s += __shfl_xor_sync(0xffffffffu, s, 8);
    s += __shfl_xor_sync(0xffffffffu, s, 4);
    s += __shfl_xor_sync(0xffffffffu, s, 2);
    s += __shfl_xor_sync(0xffffffffu, s, 1);
    if (lane == 0) g_norm[row] = 0.5f * s;
}

// ---------------- K4: kNN candidates — 4 key quarters, 2 CTAs/SM, col-half sc ----------------
#define KQ0 0
#define KK0 34816
#define KNR 69632          // 128 f32
#define KNN_SMEM 70144

__global__ __launch_bounds__(256, 2) void knn_mma_kernel()
{
    extern __shared__ __align__(16) char smc[];
    const uint32_t sb = smem_u32(smc);
    float* nr_s = reinterpret_cast<float*>(smc + KNR);

    const int tid  = threadIdx.x, wid = tid >> 5, lane = tid & 31;
    const int qbase = blockIdx.x * 128;
    const int kofs  = blockIdx.y * QUARTN;

    ld_tile_async(sb + KQ0, g_hb0 + (size_t)qbase * CC, tid);
    CP_COMMIT();

    const int r0   = wid * 16;
    const int qrow = lane >> 2, qc = (lane & 3) * 2;
    const int gr0  = qbase + r0 + qrow, gr1 = gr0 + 8;
    const int lr0  = r0 + qrow, lr1 = lr0 + 8;
    const int slot = lane & 3;

    const uint32_t aoff = (uint32_t)((r0 + (lane & 15)) * 272 + ((lane >> 4) & 1) * 16);
    const uint32_t boff = (uint32_t)(((lane & 7) + ((lane >> 4) & 1) * 8) * 272 + ((lane >> 3) & 1) * 16);

    float tv0[8], tv1[8];
    int   ti0[8], ti1[8];
    #pragma unroll
    for (int t = 0; t < 8; t++) { tv0[t] = -3e38f; tv1[t] = -3e38f; ti0[t] = 0; ti1[t] = 0; }
    float vmin0 = -3e38f, vmin1 = -3e38f;

    for (int t = 0; t < NTQ; t++) {
        const int kb = t * 128;
        ld_tile_async(sb + KK0, g_hb0 + (size_t)(kofs + kb) * CC, tid);
        CP_COMMIT();
        if (tid < 128) nr_s[tid] = g_norm[kofs + kb + tid];
        CP_WAIT(0);
        __syncthreads();

        const bool hasdiag = (kofs + kb == qbase);

        // two column halves: sc is 8x4 (32 regs) per half
        #pragma unroll
        for (int half = 0; half < 2; half++) {
            float sc[8][4];

            #pragma unroll
            for (int kc = 0; kc < 8; kc++) {
                uint32_t a[4];
                ldsm4(a, sb + KQ0 + aoff + kc * 32);
                if (kc == 0) {
                    #pragma unroll
                    for (int n2 = 0; n2 < 4; n2++) {
                        uint32_t b[4];
                        ldsm4(b, sb + KK0 + (uint32_t)((half * 4 + n2) * 16 * 272) + boff);
                        mma16816z(sc[2 * n2],     a, b[0], b[1]);
                        mma16816z(sc[2 * n2 + 1], a, b[2], b[3]);
                    }
                } else {
                    #pragma unroll
                    for (int n2 = 0; n2 < 4; n2++) {
                        uint32_t b[4];
                        ldsm4(b, sb + KK0 + (uint32_t)((half * 4 + n2) * 16 * 272) + boff + kc * 32);
                        mma16816(sc[2 * n2],     a, b[0], b[1]);
                        mma16816(sc[2 * n2 + 1], a, b[2], b[3]);
                    }
                }
            }

            // adjust by norms, mask diag (rare uniform), row maxes, rare insert
            #pragma unroll
            for (int s2 = 0; s2 < 8; s2++) {
                int c = (half * 8 + s2) * 8 + qc;
                float nr0 = nr_s[c], nr1 = nr_s[c + 1];
                sc[s2][0] -= nr0;
                sc[s2][1] -= nr1;
                sc[s2][2] -= nr0;
                sc[s2][3] -= nr1;
            }
            if (hasdiag) {
                #pragma unroll
                for (int s2 = 0; s2 < 8; s2++) {
                    int gc = kofs + kb + (half * 8 + s2) * 8 + qc;
                    if (gr0 == gc)     sc[s2][0] = -3e38f;
                    if (gr0 == gc + 1) sc[s2][1] = -3e38f;
                    if (gr1 == gc)     sc[s2][2] = -3e38f;
                    if (gr1 == gc + 1) sc[s2][3] = -3e38f;
                }
            }
            float m0 = -3e38f, m1 = -3e38f;
            #pragma unroll
            for (int s2 = 0; s2 < 8; s2++) {
                m0 = fmaxf(m0, fmaxf(sc[s2][0], sc[s2][1]));
                m1 = fmaxf(m1, fmaxf(sc[s2][2], sc[s2][3]));
            }
            if (m0 > vmin0) {
                #pragma unroll
                for (int s2 = 0; s2 < 8; s2++) {
                    int gc = kofs + kb + (half * 8 + s2) * 8 + qc;
                    if (sc[s2][0] > vmin0) { ins8(tv0, ti0, sc[s2][0], gc);     vmin0 = tv0[7]; }
                    if (sc[s2][1] > vmin0) { ins8(tv0, ti0, sc[s2][1], gc + 1); vmin0 = tv0[7]; }
                }
            }
            if (m1 > vmin1) {
                #pragma unroll
                for (int s2 = 0; s2 < 8; s2++) {
                    int gc = kofs + kb + (half * 8 + s2) * 8 + qc;
                    if (sc[s2][2] > vmin1) { ins8(tv1, ti1, sc[s2][2], gc);     vmin1 = tv1[7]; }
                    if (sc[s2][3] > vmin1) { ins8(tv1, ti1, sc[s2][3], gc + 1); vmin1 = tv1[7]; }
                }
            }
        }
        __syncthreads();   // ldsm reads done before next tile's cp.async overwrite
    }

    // merge: 4 threads x 8 entries per row -> smem -> top-8 per row (per quarter)
    float* mv = reinterpret_cast<float*>(smc);            // [128][32]
    int*   mi = reinterpret_cast<int*>(smc + 16384);      // [128][32]
    #pragma unroll
    for (int t = 0; t < 8; t++) {
        mv[lr0 * 32 + slot * 8 + t] = tv0[t];
        mi[lr0 * 32 + slot * 8 + t] = ti0[t];
        mv[lr1 * 32 + slot * 8 + t] = tv1[t];
        mi[lr1 * 32 + slot * 8 + t] = ti1[t];
    }
    __syncthreads();

    if (tid < 128) {
        const float* rv = mv + tid * 32;
        const int*   ri = mi + tid * 32;
        float bv[NCQ]; int bi[NCQ];
        #pragma unroll
        for (int t = 0; t < NCQ; t++) { bv[t] = -3e38f; bi[t] = 0; }
        float vm = -3e38f;
        #pragma unroll 4
        for (int j = 0; j < 32; j++) {
            float v = rv[j];
            if (v > vm) {
                float cv = v; int ci2 = ri[j];
                #pragma unroll
                for (int t = 0; t < NCQ; t++) {
                    if (cv > bv[t]) {
                        float a = bv[t]; bv[t] = cv; cv = a;
                        int   b = bi[t]; bi[t] = ci2; ci2 = b;
                    }
                }
                vm = bv[NCQ - 1];
            }
        }
        int* outi = g_ci8 + ((size_t)blockIdx.y * NN + qbase + tid) * NCQ;
        #pragma unroll
        for (int t = 0; t < NCQ; t++) outi[t] = bi[t];
    }
}

// ---------------- K5: exact fp32 rescore of 32 candidates (4 quarters x 8) -> top-7 ----------------
__global__ __launch_bounds__(256) void knn_rescore_kernel()
{
    int node = (blockIdx.x * 256 + threadIdx.x) >> 5;
    int lane = threadIdx.x & 31;

    float4 hv = *reinterpret_cast<const float4*>(g_h + (size_t)node * CC + lane * 4);
    int quarter = lane >> 3, slot = lane & 7;
    int ci = g_ci8[((size_t)quarter * NN + node) * NCQ + slot];

    float myv = -3e38f;
    for (int c = 0; c < 32; c++) {
        int cj = __shfl_sync(0xffffffffu, ci, c);
        float4 hc = *reinterpret_cast<const float4*>(g_h + (size_t)cj * CC + lane * 4);
        float p = hv.x * hc.x + hv.y * hc.y + hv.z * hc.z + hv.w * hc.w;
        #pragma unroll
        for (int m = 16; m >= 1; m >>= 1) p += __shfl_xor_sync(0xffffffffu, p, m);
        if (lane == c) myv = p - g_norm[cj];
    }

    float v = myv; int idx = ci;
    #pragma unroll
    for (int t = 0; t < KNBR; t++) {
        float bv = v; int bidx = idx;
        #pragma unroll
        for (int m = 16; m >= 1; m >>= 1) {
            float ov = __shfl_xor_sync(0xffffffffu, bv, m);
            int   oi = __shfl_xor_sync(0xffffffffu, bidx, m);
            if (ov > bv || (ov == bv && oi < bidx)) { bv = ov; bidx = oi; }
        }
        if (lane == 0) g_idx[node * KNBR + t] = bidx;
        if (idx == bidx) v = -3.3e38f;
    }
}

// ---------------- K6: m1 = h @ W1 ----------------
__global__ __launch_bounds__(256) void gcn1_gemm(const float* __restrict__ W1)
{
    __shared__ float xs[32 * 129];
    const int tid = threadIdx.x;
    const int r0  = blockIdx.x * 32;

    for (int i = tid; i < 32 * CC; i += 256) {
        int r = i >> 7, c = i & 127;
        xs[r * 129 + c] = g_h[(r0 + r) * CC + c];
    }
    __syncthreads();

    const int ri = (tid >> 5) * 4;
    const int c0 = (tid & 31) * 4;

    ull acc[4][2];
    #pragma unroll
    for (int i = 0; i < 4; i++) { acc[i][0] = 0ULL; acc[i][1] = 0ULL; }

    #pragma unroll 4
    for (int k2 = 0; k2 < CC; k2++) {
        ulonglong2 wp = *reinterpret_cast<const ulonglong2*>(W1 + k2 * CC + c0);
        #pragma unroll
        for (int dr = 0; dr < 4; dr++) {
            ull x2 = dup2(xs[(ri + dr) * 129 + k2]);
            acc[dr][0] = ffma2(x2, wp.x, acc[dr][0]);
            acc[dr][1] = ffma2(x2, wp.y, acc[dr][1]);
        }
    }
    #pragma unroll
    for (int dr = 0; dr < 4; dr++) {
        float2 a0 = upk(acc[dr][0]), a1 = upk(acc[dr][1]);
        float4 o = {a0.x, a0.y, a1.x, a1.y};
        *reinterpret_cast<float4*>(g_m1 + (r0 + ri + dr) * CC + c0) = o;
    }
}

// ---------------- K7: GCN layer-1 gather + relu ----------------
__global__ __launch_bounds__(128) void gather1(const float* __restrict__ b1)
{
    int node = blockIdx.x;
    int c    = threadIdx.x;
    float s = g_m1[node * CC + c];
    #pragma unroll
    for (int t = 0; t < KNBR; t++) {
        int nb = g_idx[node * KNBR + t];
        s += g_m1[nb * CC + c];
    }
    g_h1[node * CC + c] = fmaxf(s * 0.125f + b1[c], 0.f);
}

// ---------------- K8: m2 = h1 @ W2 ----------------
__global__ __launch_bounds__(256) void m2_kernel(const float* __restrict__ W2)
{
    int row  = blockIdx.x * 8 + (threadIdx.x >> 5);
    int lane = threadIdx.x & 31;
    float s = 0.f;
    for (int c = lane; c < CC; c += 32) s += g_h1[row * CC + c] * W2[c];
    s += __shfl_xor_sync(0xffffffffu, s, 16);
    s += __shfl_xor_sync(0xffffffffu, s, 8);
    s += __shfl_xor_sync(0xffffffffu, s, 4);
    s += __shfl_xor_sync(0xffffffffu, s, 2);
    s += __shfl_xor_sync(0xffffffffu, s, 1);
    if (lane == 0) g_m2[row] = s;
}

// ---------------- K9: GCN layer-2 gather -> output ----------------
__global__ __launch_bounds__(256) void out_kernel(const float* __restrict__ b2,
                                                  float* __restrict__ out)
{
    int n = blockIdx.x * 256 + threadIdx.x;
    float s = g_m2[n];
    #pragma unroll
    for (int t = 0; t < KNBR; t++) s += g_m2[g_idx[n * KNBR + t]];
    out[n] = s * 0.125f + b2[0];
}

// ---------------- launch ----------------
extern "C" void kernel_launch(void* const* d_in, const int* in_sizes, int n_in,
                              void* d_out, int out_size)
{
    const float* x   = (const float*)d_in[0];
    const float* Wq  = (const float*)d_in[1];
    const float* bq  = (const float*)d_in[2];
    const float* Wk  = (const float*)d_in[3];
    const float* bk  = (const float*)d_in[4];
    const float* Wv  = (const float*)d_in[5];
    const float* bv  = (const float*)d_in[6];
    const float* Wsk = (const float*)d_in[7];
    const float* bsk = (const float*)d_in[8];
    const float* W1  = (const float*)d_in[9];
    const float* b1  = (const float*)d_in[10];
    const float* W2  = (const float*)d_in[11];
    const float* b2  = (const float*)d_in[12];
    float* out = (float*)d_out;

    cudaFuncSetAttribute(attn_mma_kernel, cudaFuncAttributeMaxDynamicSharedMemorySize, ATTN_SMEM);
    cudaFuncSetAttribute(knn_mma_kernel,  cudaFuncAttributeMaxDynamicSharedMemorySize, KNN_SMEM);

    proj_kernel<<<NN / 32, 256>>>(x, Wq, bq, Wk, bk, Wv, bv, Wsk, bsk);
    attn_mma_kernel<<<dim3(NN / 128, 2), 256, ATTN_SMEM>>>();
    combine_norm_kernel<<<NN / 8, 256>>>();
    knn_mma_kernel<<<dim3(NN / 128, 4), 256, KNN_SMEM>>>();
    knn_rescore_kernel<<<NN / 8, 256>>>();
    gcn1_gemm<<<NN / 32, 256>>>(W1);
    gather1<<<NN, CC>>>(b1);
    m2_kernel<<<NN / 8, 256>>>(W2);
    out_kernel<<<NN / 256, 256>>>(b2, out);
}